// round 2
// baseline (speedup 1.0000x reference)
#include <cuda_runtime.h>

#define N_NODES 32768
#define F_DIM   128
#define C_CH    4
#define H_HEADS 8
#define D_DIM   32
#define DM      256
#define CHN     32          // C*H
#define E_EDGES 65536
#define B_BRIDGE 8192
#define ET      (E_EDGES + 2*B_BRIDGE)   // 81920

typedef unsigned long long u64;
union F2U { u64 u; float2 f; };

__device__ __forceinline__ u64 ffma2(u64 a, u64 b, u64 c) {
    u64 d;
    asm("fma.rn.f32x2 %0, %1, %2, %3;" : "=l"(d) : "l"(a), "l"(b), "l"(c));
    return d;
}

// ---------------- device scratch (static, no allocation) ----------------
__device__ float g_xl[(size_t)N_NODES * DM];          // 33.5 MB
__device__ float g_exps[(size_t)ET * CHN];            // 10.5 MB
__device__ float g_denom[(size_t)N_NODES * CHN];      //  4.2 MB
__device__ float g_pe[C_CH * DM];                     //  4 KB

// ---------------- init: zero denom, compute sinusoidal PE ----------------
__global__ void init_kernel() {
    int gid = blockIdx.x * 256 + threadIdx.x;
    if (gid < N_NODES * CHN) g_denom[gid] = 0.f;
    if (gid < C_CH * DM) {
        int c  = gid >> 8;
        int hd = gid & 255;
        float di  = (float)(hd & ~1);
        float div = powf(10000.f, di / 256.f);
        float ang = (float)c / div;
        g_pe[gid] = (hd & 1) ? cosf(ang) : sinf(ang);
    }
}

// ---------------- fused GEMM (packed f32x2 FMA) ---------------------------
// xl = x@W_in.T ; out = x@W_res.T + bias
// M=32768, K=128, Ncols=1280 (cols [0,256)->g_xl, [256,1280)->d_out)
// Block tile: 256m x 64n, K-chunk 16. Thread: 16m x 4n via 32 FFMA2 per k.
#define M_BLK 256
#define N_BLK 64
#define K_CHK 16

__global__ __launch_bounds__(256, 2) void gemm_kernel(
    const float* __restrict__ x, const float* __restrict__ W_in,
    const float* __restrict__ W_res, const float* __restrict__ bias,
    float* __restrict__ out)
{
    __shared__ __align__(16) float As[K_CHK][M_BLK + 4];       // [k][m] pairs along m
    __shared__ __align__(16) float Bs[K_CHK][2 * N_BLK + 4];   // [k][2j] = [k][2j+1] = b_j
    const int tid = threadIdx.x;
    const int tx = tid & 15, ty = tid >> 4;
    const int m0 = blockIdx.y * M_BLK;
    const int n0 = blockIdx.x * N_BLK;

    u64 acc[8][4];
    #pragma unroll
    for (int i = 0; i < 8; i++)
        #pragma unroll
        for (int j = 0; j < 4; j++) acc[i][j] = 0ull;

    for (int kb = 0; kb < 128; kb += K_CHK) {
        // stage A: 256m x 16k = 1024 float4 (each float4 spans 4 k's)
        #pragma unroll
        for (int r = 0; r < 4; r++) {
            int li  = tid + r * 256;
            int row = li >> 2;
            int kc  = (li & 3) << 2;
            float4 av = *(const float4*)(x + (size_t)(m0 + row) * 128 + kb + kc);
            As[kc  ][row] = av.x; As[kc+1][row] = av.y;
            As[kc+2][row] = av.z; As[kc+3][row] = av.w;
        }
        // stage B (duplicated pairs): 64n x 16k = 256 float4
        {
            int j  = tid >> 2;
            int kc = (tid & 3) << 2;
            int jg = n0 + j;
            const float* wrow = (jg < 256) ? (W_in  + (size_t)jg * 128)
                                           : (W_res + (size_t)(jg - 256) * 128);
            float4 bv = *(const float4*)(wrow + kb + kc);
            Bs[kc  ][2*j] = bv.x; Bs[kc  ][2*j+1] = bv.x;
            Bs[kc+1][2*j] = bv.y; Bs[kc+1][2*j+1] = bv.y;
            Bs[kc+2][2*j] = bv.z; Bs[kc+2][2*j+1] = bv.z;
            Bs[kc+3][2*j] = bv.w; Bs[kc+3][2*j+1] = bv.w;
        }
        __syncthreads();
        #pragma unroll
        for (int k = 0; k < K_CHK; k++) {
            ulonglong2 a01 = *(const ulonglong2*)&As[k][ty * 16];
            ulonglong2 a23 = *(const ulonglong2*)&As[k][ty * 16 + 4];
            ulonglong2 a45 = *(const ulonglong2*)&As[k][ty * 16 + 8];
            ulonglong2 a67 = *(const ulonglong2*)&As[k][ty * 16 + 12];
            ulonglong2 b01 = *(const ulonglong2*)&Bs[k][tx * 8];
            ulonglong2 b23 = *(const ulonglong2*)&Bs[k][tx * 8 + 4];
            u64 a[8] = {a01.x, a01.y, a23.x, a23.y, a45.x, a45.y, a67.x, a67.y};
            u64 b[4] = {b01.x, b01.y, b23.x, b23.y};
            #pragma unroll
            for (int ip = 0; ip < 8; ip++)
                #pragma unroll
                for (int j = 0; j < 4; j++)
                    acc[ip][j] = ffma2(a[ip], b[j], acc[ip][j]);
        }
        __syncthreads();
    }

    const int n = n0 + tx * 4;
    #pragma unroll
    for (int ip = 0; ip < 8; ip++) {
        int m = m0 + ty * 16 + ip * 2;
        F2U u0, u1, u2, u3;
        u0.u = acc[ip][0]; u1.u = acc[ip][1]; u2.u = acc[ip][2]; u3.u = acc[ip][3];
        float4 ve = make_float4(u0.f.x, u1.f.x, u2.f.x, u3.f.x);  // row m
        float4 vo = make_float4(u0.f.y, u1.f.y, u2.f.y, u3.f.y);  // row m+1
        if (n < 256) {
            *(float4*)(g_xl + (size_t)m * 256 + n)       = ve;
            *(float4*)(g_xl + (size_t)(m + 1) * 256 + n) = vo;
        } else {
            const float4 bb = *(const float4*)(bias + (n - 256));
            ve.x += bb.x; ve.y += bb.y; ve.z += bb.z; ve.w += bb.w;
            vo.x += bb.x; vo.y += bb.y; vo.z += bb.z; vo.w += bb.w;
            *(float4*)(out + (size_t)m * 1024 + (n - 256))       = ve;
            *(float4*)(out + (size_t)(m + 1) * 1024 + (n - 256)) = vo;
        }
    }
}

// ---------------- scores + denom: one warp per edge ----------------------
__global__ __launch_bounds__(256) void scores_kernel(
    const int* __restrict__ edge_index, const int* __restrict__ bridge_index,
    const float* __restrict__ double_attn)
{
    __shared__ float pe_s[1024];
    __shared__ float aw_s[1024];
    for (int i = threadIdx.x; i < 1024; i += 256) {
        pe_s[i] = g_pe[i];
        aw_s[i] = double_attn[i];
    }
    __syncthreads();
    const int e    = (blockIdx.x * 256 + threadIdx.x) >> 5;
    const int lane = threadIdx.x & 31;

    int u, v, dst, type;
    if (e < E_EDGES)                { u = edge_index[e];   v = edge_index[E_EDGES + e];   dst = v; type = 0; }
    else if (e < E_EDGES + B_BRIDGE){ int i = e - E_EDGES;            u = bridge_index[i]; v = bridge_index[B_BRIDGE + i]; dst = v; type = 1; }
    else                            { int i = e - E_EDGES - B_BRIDGE; u = bridge_index[i]; v = bridge_index[B_BRIDGE + i]; dst = u; type = 2; }

    const float* xu = g_xl + (size_t)u * DM;
    const float* xv = g_xl + (size_t)v * DM;
    float S[8];
    #pragma unroll
    for (int h = 0; h < 8; h++) S[h] = xu[h * 32 + lane] + xv[h * 32 + lane];

    float myscore = 0.f;
    #pragma unroll
    for (int ch = 0; ch < 32; ch++) {
        const int c = ch >> 3, h = ch & 7;
        int c2;
        if (type == 0)      c2 = c;
        else if (type == 1) c2 = (c < 3) ? c + 1 : 3;
        else                c2 = (c > 0) ? c - 1 : 0;
        float t = S[h] + pe_s[c * 256 + h * 32 + lane] + pe_s[c2 * 256 + h * 32 + lane];
        t = (t >= 0.f) ? t : 0.2f * t;                       // leaky(0.2)
        bool masked = (type == 1 && c == 3) || (type == 2 && c == 0);
        float prod = masked ? 0.f : t * aw_s[ch * 32 + lane];
        #pragma unroll
        for (int off = 16; off; off >>= 1)
            prod += __shfl_xor_sync(0xffffffffu, prod, off);
        if (lane == ch) myscore = prod;
    }
    float ex = expf(myscore);   // global-max shift omitted: alpha-invariant (eps ~1e-16)
    g_exps[(size_t)e * 32 + lane] = ex;
    atomicAdd(&g_denom[(size_t)dst * 32 + lane], ex);
}

// ---------------- scatter: proj accumulation via vectorized red ----------
__device__ __forceinline__ void red_add_v4(float* p, float4 v) {
    asm volatile("red.global.add.v4.f32 [%0], {%1,%2,%3,%4};"
                 :: "l"(p), "f"(v.x), "f"(v.y), "f"(v.z), "f"(v.w) : "memory");
}

__global__ __launch_bounds__(256) void scatter_kernel(
    const int* __restrict__ edge_index, const int* __restrict__ bridge_index,
    float* __restrict__ out)
{
    __shared__ __align__(16) float pe_s[1024];
    for (int i = threadIdx.x; i < 1024; i += 256) pe_s[i] = g_pe[i];
    __syncthreads();
    const int e    = (blockIdx.x * 256 + threadIdx.x) >> 5;
    const int lane = threadIdx.x & 31;

    int fs, dst;
    if (e < E_EDGES)                 { fs = edge_index[e];              dst = edge_index[E_EDGES + e]; }
    else if (e < E_EDGES + B_BRIDGE) { int i = e - E_EDGES;             fs = bridge_index[i];            dst = bridge_index[B_BRIDGE + i]; }
    else                             { int i = e - E_EDGES - B_BRIDGE;  fs = bridge_index[B_BRIDGE + i]; dst = bridge_index[i]; }

    // faithful reference bug: x_src[full_src[e]] == xr[edge_index[0][full_src[e]]]
    const int s2 = edge_index[fs];

    float a = g_exps[(size_t)e * 32 + lane] /
              (g_denom[(size_t)dst * 32 + lane] + 1e-16f);

    const float4* xs = (const float4*)(g_xl + (size_t)s2 * DM);
    const int q = lane & 7;          // which float4 within a head row
    const int g = lane >> 3;         // chain index c for this lane group
    float4 xv[8];
    #pragma unroll
    for (int h = 0; h < 8; h++) xv[h] = xs[h * 8 + q];

    float* ob = out + (size_t)dst * 1024;
    #pragma unroll
    for (int it = 0; it < 8; it++) {     // it = head h (static reg index)
        const int ch = g * 8 + it;       // c = g, h = it
        float ach = __shfl_sync(0xffffffffu, a, ch);
        float4 p = *(const float4*)(pe_s + g * 256 + it * 32 + q * 4);
        float4 vv;
        vv.x = (xv[it].x + p.x) * ach;
        vv.y = (xv[it].y + p.y) * ach;
        vv.z = (xv[it].z + p.z) * ach;
        vv.w = (xv[it].w + p.w) * ach;
        red_add_v4(ob + ch * 32 + q * 4, vv);
    }
}

// ---------------- final PReLU -------------------------------------------
__global__ void prelu_kernel(float* __restrict__ out, const float* __restrict__ pw) {
    const float w = pw[0];
    size_t i = ((size_t)blockIdx.x * 256 + threadIdx.x) * 4;
    float4 v = *(float4*)(out + i);
    v.x = (v.x >= 0.f) ? v.x : w * v.x;
    v.y = (v.y >= 0.f) ? v.y : w * v.y;
    v.z = (v.z >= 0.f) ? v.z : w * v.z;
    v.w = (v.w >= 0.f) ? v.w : w * v.w;
    *(float4*)(out + i) = v;
}

// ---------------- launch --------------------------------------------------
extern "C" void kernel_launch(void* const* d_in, const int* in_sizes, int n_in,
                              void* d_out, int out_size) {
    const float* x            = (const float*)d_in[0];
    const int*   edge_index   = (const int*)  d_in[1];
    const int*   bridge_index = (const int*)  d_in[2];
    const float* W_in         = (const float*)d_in[3];
    const float* double_attn  = (const float*)d_in[4];
    const float* W_res        = (const float*)d_in[5];
    const float* bias         = (const float*)d_in[6];
    const float* prelu_w      = (const float*)d_in[7];
    float* out = (float*)d_out;

    init_kernel<<<4096, 256>>>();
    gemm_kernel<<<dim3(20, 128), 256>>>(x, W_in, W_res, bias, out);
    scores_kernel<<<ET / 8, 256>>>(edge_index, bridge_index, double_attn);
    scatter_kernel<<<ET / 8, 256>>>(edge_index, bridge_index, out);
    prelu_kernel<<<(N_NODES * 1024) / (256 * 4), 256>>>(out, prelu_w);
}

// round 4
// speedup vs baseline: 1.5359x; 1.5359x over previous
#include <cuda_runtime.h>
#include <cuda_bf16.h>
#include <cstdint>

#define N_NODES 32768
#define F_DIM   128
#define C_CH    4
#define H_HEADS 8
#define D_DIM   32
#define DM      256
#define CHN     32          // C*H
#define E_EDGES 65536
#define B_BRIDGE 8192
#define ET      (E_EDGES + 2*B_BRIDGE)   // 81920

// ---------------- device scratch (static, no allocation) ----------------
__device__ float g_xl[(size_t)N_NODES * DM];          // 33.5 MB
__device__ float g_exps[(size_t)ET * CHN];            // 10.5 MB
__device__ float g_denom[(size_t)N_NODES * CHN];      //  4.2 MB
__device__ float g_pe[C_CH * DM];                     //  4 KB

// ---------------- init: zero denom, compute sinusoidal PE ----------------
__global__ void init_kernel() {
    int gid = blockIdx.x * 256 + threadIdx.x;
    if (gid < N_NODES * CHN) g_denom[gid] = 0.f;
    if (gid < C_CH * DM) {
        int c  = gid >> 8;
        int hd = gid & 255;
        float di  = (float)(hd & ~1);
        float div = powf(10000.f, di / 256.f);
        float ang = (float)c / div;
        g_pe[gid] = (hd & 1) ? cosf(ang) : sinf(ang);
    }
}

// ============== bf16-split mma.sync GEMM ==================================
// C[32768,1280] = X[32768,128] @ W^T, W = [W_in; W_res] (1280 x 128).
// Split: X = Xhi + Xlo (bf16 each); C ~= Xhi Whi + Xhi Wlo + Xlo Whi.
// Block: 128m x 128n, K chunked 2x64. Warp: 64m x 32n via m16n8k16.

#define MB 128
#define NB 128
#define KC 64
#define AST 72      // bf16 row stride (72*2=144B): bank = 4*row + k', conflict-free
#define GEMM_SMEM (4 * MB * AST * 2)   // Ahi,Alo,Bhi,Blo = 73728 B

__device__ __forceinline__ void mma_bf16(float* c, const uint32_t* a,
                                         uint32_t b0, uint32_t b1) {
    asm volatile(
        "mma.sync.aligned.m16n8k16.row.col.f32.bf16.bf16.f32 "
        "{%0,%1,%2,%3}, {%4,%5,%6,%7}, {%8,%9}, {%0,%1,%2,%3};"
        : "+f"(c[0]), "+f"(c[1]), "+f"(c[2]), "+f"(c[3])
        : "r"(a[0]), "r"(a[1]), "r"(a[2]), "r"(a[3]), "r"(b0), "r"(b1));
}

__global__ void __launch_bounds__(256, 2) gemm_mma_kernel(
    const float* __restrict__ x, const float* __restrict__ W_in,
    const float* __restrict__ W_res, const float* __restrict__ bias,
    float* __restrict__ out)
{
    extern __shared__ __align__(16) char smem[];
    __nv_bfloat16* Ahi = (__nv_bfloat16*)smem;          // [128][72]
    __nv_bfloat16* Alo = Ahi + MB * AST;
    __nv_bfloat16* Bhi = Alo + MB * AST;
    __nv_bfloat16* Blo = Bhi + NB * AST;

    const int tid  = threadIdx.x;
    const int wid  = tid >> 5, lane = tid & 31;
    const int wr   = wid & 1;          // warp row: 0..1 (64 rows each)
    const int wc   = wid >> 1;         // warp col: 0..3 (32 cols each)
    const int m0   = blockIdx.y * MB;
    const int nb   = blockIdx.x;       // 0..9
    const int n0g  = nb * NB;

    // W rows n0g..n0g+127 come entirely from W_in (nb<2) or W_res (nb>=2)
    const float* wbase = (nb < 2) ? (W_in + (size_t)n0g * 128)
                                  : (W_res + (size_t)(n0g - 256) * 128);

    float acc[4][4][4];
    #pragma unroll
    for (int a = 0; a < 4; a++)
        #pragma unroll
        for (int b = 0; b < 4; b++)
            #pragma unroll
            for (int cc = 0; cc < 4; cc++) acc[a][b][cc] = 0.f;

    for (int kk = 0; kk < 128; kk += KC) {
        if (kk) __syncthreads();
        // stage A: X[128 rows m0..][64 cols kk..] -> Ahi/Alo
        #pragma unroll
        for (int r = 0; r < 8; r++) {
            int i   = tid + r * 256;       // 2048 float4
            int row = i >> 4;
            int c4  = (i & 15) << 2;
            float4 v = *(const float4*)(x + (size_t)(m0 + row) * 128 + kk + c4);
            __nv_bfloat162 h0 = __floats2bfloat162_rn(v.x, v.y);
            __nv_bfloat162 h1 = __floats2bfloat162_rn(v.z, v.w);
            __nv_bfloat162 l0 = __floats2bfloat162_rn(v.x - __bfloat162float(h0.x),
                                                      v.y - __bfloat162float(h0.y));
            __nv_bfloat162 l1 = __floats2bfloat162_rn(v.z - __bfloat162float(h1.x),
                                                      v.w - __bfloat162float(h1.y));
            *(__nv_bfloat162*)(Ahi + row * AST + c4)     = h0;
            *(__nv_bfloat162*)(Ahi + row * AST + c4 + 2) = h1;
            *(__nv_bfloat162*)(Alo + row * AST + c4)     = l0;
            *(__nv_bfloat162*)(Alo + row * AST + c4 + 2) = l1;
        }
        // stage B: W[128 rows n0g..][64 cols kk..] -> Bhi/Blo
        #pragma unroll
        for (int r = 0; r < 8; r++) {
            int i   = tid + r * 256;
            int row = i >> 4;
            int c4  = (i & 15) << 2;
            float4 v = *(const float4*)(wbase + (size_t)row * 128 + kk + c4);
            __nv_bfloat162 h0 = __floats2bfloat162_rn(v.x, v.y);
            __nv_bfloat162 h1 = __floats2bfloat162_rn(v.z, v.w);
            __nv_bfloat162 l0 = __floats2bfloat162_rn(v.x - __bfloat162float(h0.x),
                                                      v.y - __bfloat162float(h0.y));
            __nv_bfloat162 l1 = __floats2bfloat162_rn(v.z - __bfloat162float(h1.x),
                                                      v.w - __bfloat162float(h1.y));
            *(__nv_bfloat162*)(Bhi + row * AST + c4)     = h0;
            *(__nv_bfloat162*)(Bhi + row * AST + c4 + 2) = h1;
            *(__nv_bfloat162*)(Blo + row * AST + c4)     = l0;
            *(__nv_bfloat162*)(Blo + row * AST + c4 + 2) = l1;
        }
        __syncthreads();

        const int mrow = wr * 64 + (lane >> 2);
        #pragma unroll
        for (int ks = 0; ks < 4; ks++) {
            const int kb = ks * 16 + 2 * (lane & 3);
            uint32_t ah[4][4], al[4][4];
            #pragma unroll
            for (int mi = 0; mi < 4; mi++) {
                int m = mrow + mi * 16;
                ah[mi][0] = *(const uint32_t*)(Ahi + m * AST + kb);
                ah[mi][1] = *(const uint32_t*)(Ahi + (m + 8) * AST + kb);
                ah[mi][2] = *(const uint32_t*)(Ahi + m * AST + kb + 8);
                ah[mi][3] = *(const uint32_t*)(Ahi + (m + 8) * AST + kb + 8);
                al[mi][0] = *(const uint32_t*)(Alo + m * AST + kb);
                al[mi][1] = *(const uint32_t*)(Alo + (m + 8) * AST + kb);
                al[mi][2] = *(const uint32_t*)(Alo + m * AST + kb + 8);
                al[mi][3] = *(const uint32_t*)(Alo + (m + 8) * AST + kb + 8);
            }
            #pragma unroll
            for (int ni = 0; ni < 4; ni++) {
                int n = wc * 32 + ni * 8 + (lane >> 2);
                uint32_t bh0 = *(const uint32_t*)(Bhi + n * AST + kb);
                uint32_t bh1 = *(const uint32_t*)(Bhi + n * AST + kb + 8);
                uint32_t bl0 = *(const uint32_t*)(Blo + n * AST + kb);
                uint32_t bl1 = *(const uint32_t*)(Blo + n * AST + kb + 8);
                #pragma unroll
                for (int mi = 0; mi < 4; mi++) {
                    mma_bf16(acc[mi][ni], ah[mi], bh0, bh1);
                    mma_bf16(acc[mi][ni], ah[mi], bl0, bl1);
                    mma_bf16(acc[mi][ni], al[mi], bh0, bh1);
                }
            }
        }
    }

    // epilogue: thread owns (m, n), (m+8, n) with n = 2 cols
    const int mrow = m0 + wr * 64 + (lane >> 2);
    const int ncol = wc * 32 + 2 * (lane & 3);
    #pragma unroll
    for (int mi = 0; mi < 4; mi++) {
        #pragma unroll
        for (int ni = 0; ni < 4; ni++) {
            int m = mrow + mi * 16;
            int nl = ncol + ni * 8;
            float* c = acc[mi][ni];
            if (nb < 2) {
                int col = n0g + nl;
                *(float2*)(g_xl + (size_t)m * 256 + col)       = make_float2(c[0], c[1]);
                *(float2*)(g_xl + (size_t)(m + 8) * 256 + col) = make_float2(c[2], c[3]);
            } else {
                int col = n0g - 256 + nl;
                float b0 = __ldg(bias + col), b1 = __ldg(bias + col + 1);
                *(float2*)(out + (size_t)m * 1024 + col)       = make_float2(c[0] + b0, c[1] + b1);
                *(float2*)(out + (size_t)(m + 8) * 1024 + col) = make_float2(c[2] + b0, c[3] + b1);
            }
        }
    }
}

// ---------------- scores + denom: one warp per edge ----------------------
__global__ __launch_bounds__(256) void scores_kernel(
    const int* __restrict__ edge_index, const int* __restrict__ bridge_index,
    const float* __restrict__ double_attn)
{
    __shared__ float pe_s[1024];
    __shared__ float aw_s[1024];
    for (int i = threadIdx.x; i < 1024; i += 256) {
        pe_s[i] = g_pe[i];
        aw_s[i] = double_attn[i];
    }
    __syncthreads();
    const int e    = (blockIdx.x * 256 + threadIdx.x) >> 5;
    const int lane = threadIdx.x & 31;

    int u, v, dst, type;
    if (e < E_EDGES)                { u = edge_index[e];   v = edge_index[E_EDGES + e];   dst = v; type = 0; }
    else if (e < E_EDGES + B_BRIDGE){ int i = e - E_EDGES;            u = bridge_index[i]; v = bridge_index[B_BRIDGE + i]; dst = v; type = 1; }
    else                            { int i = e - E_EDGES - B_BRIDGE; u = bridge_index[i]; v = bridge_index[B_BRIDGE + i]; dst = u; type = 2; }

    const float* xu = g_xl + (size_t)u * DM;
    const float* xv = g_xl + (size_t)v * DM;
    float S[8];
    #pragma unroll
    for (int h = 0; h < 8; h++) S[h] = xu[h * 32 + lane] + xv[h * 32 + lane];

    float myscore = 0.f;
    #pragma unroll
    for (int ch = 0; ch < 32; ch++) {
        const int c = ch >> 3, h = ch & 7;
        int c2;
        if (type == 0)      c2 = c;
        else if (type == 1) c2 = (c < 3) ? c + 1 : 3;
        else                c2 = (c > 0) ? c - 1 : 0;
        float t = S[h] + pe_s[c * 256 + h * 32 + lane] + pe_s[c2 * 256 + h * 32 + lane];
        t = (t >= 0.f) ? t : 0.2f * t;                       // leaky(0.2)
        bool masked = (type == 1 && c == 3) || (type == 2 && c == 0);
        float prod = masked ? 0.f : t * aw_s[ch * 32 + lane];
        #pragma unroll
        for (int off = 16; off; off >>= 1)
            prod += __shfl_xor_sync(0xffffffffu, prod, off);
        if (lane == ch) myscore = prod;
    }
    float ex = expf(myscore);   // global-max shift omitted: alpha-invariant (eps ~1e-16)
    g_exps[(size_t)e * 32 + lane] = ex;
    atomicAdd(&g_denom[(size_t)dst * 32 + lane], ex);
}

// ---------------- scatter: proj accumulation via vectorized red ----------
__device__ __forceinline__ void red_add_v4(float* p, float4 v) {
    asm volatile("red.global.add.v4.f32 [%0], {%1,%2,%3,%4};"
                 :: "l"(p), "f"(v.x), "f"(v.y), "f"(v.z), "f"(v.w) : "memory");
}

__global__ __launch_bounds__(256) void scatter_kernel(
    const int* __restrict__ edge_index, const int* __restrict__ bridge_index,
    float* __restrict__ out)
{
    __shared__ __align__(16) float pe_s[1024];
    for (int i = threadIdx.x; i < 1024; i += 256) pe_s[i] = g_pe[i];
    __syncthreads();
    const int e    = (blockIdx.x * 256 + threadIdx.x) >> 5;
    const int lane = threadIdx.x & 31;

    int fs, dst;
    if (e < E_EDGES)                 { fs = edge_index[e];              dst = edge_index[E_EDGES + e]; }
    else if (e < E_EDGES + B_BRIDGE) { int i = e - E_EDGES;             fs = bridge_index[i];            dst = bridge_index[B_BRIDGE + i]; }
    else                             { int i = e - E_EDGES - B_BRIDGE;  fs = bridge_index[B_BRIDGE + i]; dst = bridge_index[i]; }

    // faithful reference bug: x_src[full_src[e]] == xr[edge_index[0][full_src[e]]]
    const int s2 = edge_index[fs];

    float a = g_exps[(size_t)e * 32 + lane] /
              (g_denom[(size_t)dst * 32 + lane] + 1e-16f);

    const float4* xs = (const float4*)(g_xl + (size_t)s2 * DM);
    const int q = lane & 7;          // which float4 within a head row
    const int g = lane >> 3;         // chain index c for this lane group
    float4 xv[8];
    #pragma unroll
    for (int h = 0; h < 8; h++) xv[h] = xs[h * 8 + q];

    float* ob = out + (size_t)dst * 1024;
    #pragma unroll
    for (int it = 0; it < 8; it++) {     // it = head h (static reg index)
        const int ch = g * 8 + it;       // c = g, h = it
        float ach = __shfl_sync(0xffffffffu, a, ch);
        float4 p = *(const float4*)(pe_s + g * 256 + it * 32 + q * 4);
        float4 vv;
        vv.x = (xv[it].x + p.x) * ach;
        vv.y = (xv[it].y + p.y) * ach;
        vv.z = (xv[it].z + p.z) * ach;
        vv.w = (xv[it].w + p.w) * ach;
        red_add_v4(ob + ch * 32 + q * 4, vv);
    }
}

// ---------------- final PReLU -------------------------------------------
__global__ void prelu_kernel(float* __restrict__ out, const float* __restrict__ pw) {
    const float w = pw[0];
    size_t i = ((size_t)blockIdx.x * 256 + threadIdx.x) * 4;
    float4 v = *(float4*)(out + i);
    v.x = (v.x >= 0.f) ? v.x : w * v.x;
    v.y = (v.y >= 0.f) ? v.y : w * v.y;
    v.z = (v.z >= 0.f) ? v.z : w * v.z;
    v.w = (v.w >= 0.f) ? v.w : w * v.w;
    *(float4*)(out + i) = v;
}

// ---------------- launch --------------------------------------------------
extern "C" void kernel_launch(void* const* d_in, const int* in_sizes, int n_in,
                              void* d_out, int out_size) {
    const float* x            = (const float*)d_in[0];
    const int*   edge_index   = (const int*)  d_in[1];
    const int*   bridge_index = (const int*)  d_in[2];
    const float* W_in         = (const float*)d_in[3];
    const float* double_attn  = (const float*)d_in[4];
    const float* W_res        = (const float*)d_in[5];
    const float* bias         = (const float*)d_in[6];
    const float* prelu_w      = (const float*)d_in[7];
    float* out = (float*)d_out;

    cudaFuncSetAttribute(gemm_mma_kernel,
                         cudaFuncAttributeMaxDynamicSharedMemorySize, GEMM_SMEM);

    init_kernel<<<4096, 256>>>();
    gemm_mma_kernel<<<dim3(10, 256), 256, GEMM_SMEM>>>(x, W_in, W_res, bias, out);
    scores_kernel<<<ET / 8, 256>>>(edge_index, bridge_index, double_attn);
    scatter_kernel<<<ET / 8, 256>>>(edge_index, bridge_index, out);
    prelu_kernel<<<(N_NODES * 1024) / (256 * 4), 256>>>(out, prelu_w);
}

// round 5
// speedup vs baseline: 1.5749x; 1.0254x over previous
#include <cuda_runtime.h>
#include <cuda_bf16.h>
#include <cstdint>

#define N_NODES 32768
#define F_DIM   128
#define C_CH    4
#define H_HEADS 8
#define D_DIM   32
#define DM      256
#define CHN     32          // C*H
#define E_EDGES 65536
#define B_BRIDGE 8192
#define ET      (E_EDGES + 2*B_BRIDGE)   // 81920
#define NW      1280        // total W rows (W_in 256 + W_res 1024)

// ---------------- device scratch (static, no allocation) ----------------
__device__ float g_xl[(size_t)N_NODES * DM];          // 33.5 MB
__device__ float g_exps[(size_t)ET * CHN];            // 10.5 MB
__device__ float g_denom[(size_t)N_NODES * CHN];      //  4.2 MB
__device__ float g_pe[C_CH * DM];                     //  4 KB
__device__ __nv_bfloat16 g_xhi[(size_t)N_NODES * 128];  // 8.4 MB
__device__ __nv_bfloat16 g_xlo[(size_t)N_NODES * 128];  // 8.4 MB
__device__ __nv_bfloat16 g_whi[NW * 128];               // 328 KB
__device__ __nv_bfloat16 g_wlo[NW * 128];               // 328 KB

__device__ __forceinline__ uint32_t smem_u32(const void* p) {
    uint32_t a;
    asm("{ .reg .u64 t; cvta.to.shared.u64 t, %1; cvt.u32.u64 %0, t; }"
        : "=r"(a) : "l"(p));
    return a;
}
__device__ __forceinline__ void cp16(uint32_t dst, const void* src) {
    asm volatile("cp.async.ca.shared.global [%0], [%1], 16;"
                 :: "r"(dst), "l"(src) : "memory");
}

// ---------------- init: zero denom, compute sinusoidal PE ----------------
__global__ void init_kernel() {
    int gid = blockIdx.x * 256 + threadIdx.x;
    if (gid < N_NODES * CHN) g_denom[gid] = 0.f;
    if (gid < C_CH * DM) {
        int c  = gid >> 8;
        int hd = gid & 255;
        float di  = (float)(hd & ~1);
        float div = powf(10000.f, di / 256.f);
        float ang = (float)c / div;
        g_pe[gid] = (hd & 1) ? cosf(ang) : sinf(ang);
    }
}

// ---------------- prep: split X and W into bf16 hi/lo ---------------------
#define NX4 ((N_NODES * 128) / 4)     // 1,048,576 float4 of X
#define NW4 ((NW * 128) / 4)          // 40,960 float4 of W
__global__ void prep_kernel(const float* __restrict__ x,
                            const float* __restrict__ W_in,
                            const float* __restrict__ W_res) {
    int gid = blockIdx.x * 256 + threadIdx.x;
    float4 v;
    __nv_bfloat16 *hi, *lo;
    if (gid < NX4) {
        v  = ((const float4*)x)[gid];
        hi = g_xhi; lo = g_xlo;
    } else if (gid < NX4 + NW4) {
        int j   = gid - NX4;
        int row = j >> 5;             // 32 float4 per 128-col row
        int c   = j & 31;
        const float* src = (row < 256) ? (W_in + (size_t)row * 128)
                                       : (W_res + (size_t)(row - 256) * 128);
        v  = ((const float4*)src)[c];
        hi = g_whi; lo = g_wlo;
        gid = j;
    } else return;
    __nv_bfloat162 h0 = __floats2bfloat162_rn(v.x, v.y);
    __nv_bfloat162 h1 = __floats2bfloat162_rn(v.z, v.w);
    __nv_bfloat162 l0 = __floats2bfloat162_rn(v.x - __bfloat162float(h0.x),
                                              v.y - __bfloat162float(h0.y));
    __nv_bfloat162 l1 = __floats2bfloat162_rn(v.z - __bfloat162float(h1.x),
                                              v.w - __bfloat162float(h1.y));
    ((uint2*)hi)[gid] = make_uint2(*(uint32_t*)&h0, *(uint32_t*)&h1);
    ((uint2*)lo)[gid] = make_uint2(*(uint32_t*)&l0, *(uint32_t*)&l1);
}

// ============== bf16-split mma.sync GEMM (cp.async staging) ===============
// C[32768,1280] = X @ W^T; split C ~= Xhi Whi + Xhi Wlo + Xlo Whi.
// Block: 128m x 128n, K chunked 2x64. Warp: 64m x 32n via m16n8k16.
#define MB 128
#define NB 128
#define KC 64
#define AST 72      // bf16 row stride (144 B): conflict-free frag loads
#define GEMM_SMEM (4 * MB * AST * 2)   // 73728 B

__device__ __forceinline__ void mma_bf16(float* c, const uint32_t* a,
                                         uint32_t b0, uint32_t b1) {
    asm volatile(
        "mma.sync.aligned.m16n8k16.row.col.f32.bf16.bf16.f32 "
        "{%0,%1,%2,%3}, {%4,%5,%6,%7}, {%8,%9}, {%0,%1,%2,%3};"
        : "+f"(c[0]), "+f"(c[1]), "+f"(c[2]), "+f"(c[3])
        : "r"(a[0]), "r"(a[1]), "r"(a[2]), "r"(a[3]), "r"(b0), "r"(b1));
}

__global__ void __launch_bounds__(256, 2) gemm_mma_kernel(
    const float* __restrict__ bias, float* __restrict__ out, int nbase)
{
    extern __shared__ __align__(16) char smem[];
    __nv_bfloat16* Ahi = (__nv_bfloat16*)smem;          // [128][72]
    __nv_bfloat16* Alo = Ahi + MB * AST;
    __nv_bfloat16* Bhi = Alo + MB * AST;
    __nv_bfloat16* Blo = Bhi + NB * AST;

    const int tid  = threadIdx.x;
    const int wid  = tid >> 5, lane = tid & 31;
    const int wr   = wid & 1;
    const int wc   = wid >> 1;
    const int m0   = blockIdx.y * MB;
    const int nb   = nbase + blockIdx.x;
    const int n0g  = nb * NB;

    const uint32_t sAhi = smem_u32(Ahi), sAlo = smem_u32(Alo);
    const uint32_t sBhi = smem_u32(Bhi), sBlo = smem_u32(Blo);

    float acc[4][4][4];
    #pragma unroll
    for (int a = 0; a < 4; a++)
        #pragma unroll
        for (int b = 0; b < 4; b++)
            #pragma unroll
            for (int cc = 0; cc < 4; cc++) acc[a][b][cc] = 0.f;

    for (int kk = 0; kk < 128; kk += KC) {
        if (kk) __syncthreads();
        // stage via cp.async: 4 tiles x 1024 x 16B
        #pragma unroll
        for (int r = 0; r < 4; r++) {
            int i = tid + r * 256;
            int row = i >> 3, c8 = i & 7;
            uint32_t so = row * (AST * 2) + c8 * 16;
            size_t ga = (size_t)(m0 + row) * 128 + kk + c8 * 8;
            size_t gb = (size_t)(n0g + row) * 128 + kk + c8 * 8;
            cp16(sAhi + so, g_xhi + ga);
            cp16(sAlo + so, g_xlo + ga);
            cp16(sBhi + so, g_whi + gb);
            cp16(sBlo + so, g_wlo + gb);
        }
        asm volatile("cp.async.commit_group;");
        asm volatile("cp.async.wait_group 0;" ::: "memory");
        __syncthreads();

        const int mrow = wr * 64 + (lane >> 2);
        #pragma unroll
        for (int ks = 0; ks < 4; ks++) {
            const int kb = ks * 16 + 2 * (lane & 3);
            uint32_t ah[4][4], al[4][4];
            #pragma unroll
            for (int mi = 0; mi < 4; mi++) {
                int m = mrow + mi * 16;
                ah[mi][0] = *(const uint32_t*)(Ahi + m * AST + kb);
                ah[mi][1] = *(const uint32_t*)(Ahi + (m + 8) * AST + kb);
                ah[mi][2] = *(const uint32_t*)(Ahi + m * AST + kb + 8);
                ah[mi][3] = *(const uint32_t*)(Ahi + (m + 8) * AST + kb + 8);
                al[mi][0] = *(const uint32_t*)(Alo + m * AST + kb);
                al[mi][1] = *(const uint32_t*)(Alo + (m + 8) * AST + kb);
                al[mi][2] = *(const uint32_t*)(Alo + m * AST + kb + 8);
                al[mi][3] = *(const uint32_t*)(Alo + (m + 8) * AST + kb + 8);
            }
            #pragma unroll
            for (int ni = 0; ni < 4; ni++) {
                int n = wc * 32 + ni * 8 + (lane >> 2);
                uint32_t bh0 = *(const uint32_t*)(Bhi + n * AST + kb);
                uint32_t bh1 = *(const uint32_t*)(Bhi + n * AST + kb + 8);
                uint32_t bl0 = *(const uint32_t*)(Blo + n * AST + kb);
                uint32_t bl1 = *(const uint32_t*)(Blo + n * AST + kb + 8);
                #pragma unroll
                for (int mi = 0; mi < 4; mi++) {
                    mma_bf16(acc[mi][ni], ah[mi], bh0, bh1);
                    mma_bf16(acc[mi][ni], ah[mi], bl0, bl1);
                    mma_bf16(acc[mi][ni], al[mi], bh0, bh1);
                }
            }
        }
    }

    const int mrow = m0 + wr * 64 + (lane >> 2);
    const int ncol = wc * 32 + 2 * (lane & 3);
    #pragma unroll
    for (int mi = 0; mi < 4; mi++) {
        #pragma unroll
        for (int ni = 0; ni < 4; ni++) {
            int m = mrow + mi * 16;
            int nl = ncol + ni * 8;
            float* c = acc[mi][ni];
            if (nb < 2) {
                int col = n0g + nl;
                *(float2*)(g_xl + (size_t)m * 256 + col)       = make_float2(c[0], c[1]);
                *(float2*)(g_xl + (size_t)(m + 8) * 256 + col) = make_float2(c[2], c[3]);
            } else {
                int col = n0g - 256 + nl;
                float b0 = __ldg(bias + col), b1 = __ldg(bias + col + 1);
                *(float2*)(out + (size_t)m * 1024 + col)       = make_float2(c[0] + b0, c[1] + b1);
                *(float2*)(out + (size_t)(m + 8) * 1024 + col) = make_float2(c[2] + b0, c[3] + b1);
            }
        }
    }
}

// ---------------- scores + denom: one warp per edge ----------------------
__global__ __launch_bounds__(256) void scores_kernel(
    const int* __restrict__ edge_index, const int* __restrict__ bridge_index,
    const float* __restrict__ double_attn)
{
    __shared__ float pe_s[1024];
    __shared__ float aw_s[1024];
    for (int i = threadIdx.x; i < 1024; i += 256) {
        pe_s[i] = g_pe[i];
        aw_s[i] = double_attn[i];
    }
    __syncthreads();
    const int e    = (blockIdx.x * 256 + threadIdx.x) >> 5;
    const int lane = threadIdx.x & 31;

    int u, v, dst, type;
    if (e < E_EDGES)                { u = edge_index[e];   v = edge_index[E_EDGES + e];   dst = v; type = 0; }
    else if (e < E_EDGES + B_BRIDGE){ int i = e - E_EDGES;            u = bridge_index[i]; v = bridge_index[B_BRIDGE + i]; dst = v; type = 1; }
    else                            { int i = e - E_EDGES - B_BRIDGE; u = bridge_index[i]; v = bridge_index[B_BRIDGE + i]; dst = u; type = 2; }

    const float* xu = g_xl + (size_t)u * DM;
    const float* xv = g_xl + (size_t)v * DM;
    float S[8];
    #pragma unroll
    for (int h = 0; h < 8; h++) S[h] = xu[h * 32 + lane] + xv[h * 32 + lane];

    float myscore = 0.f;
    #pragma unroll
    for (int ch = 0; ch < 32; ch++) {
        const int c = ch >> 3, h = ch & 7;
        int c2;
        if (type == 0)      c2 = c;
        else if (type == 1) c2 = (c < 3) ? c + 1 : 3;
        else                c2 = (c > 0) ? c - 1 : 0;
        float t = S[h] + pe_s[c * 256 + h * 32 + lane] + pe_s[c2 * 256 + h * 32 + lane];
        t = (t >= 0.f) ? t : 0.2f * t;                       // leaky(0.2)
        bool masked = (type == 1 && c == 3) || (type == 2 && c == 0);
        float prod = masked ? 0.f : t * aw_s[ch * 32 + lane];
        #pragma unroll
        for (int off = 16; off; off >>= 1)
            prod += __shfl_xor_sync(0xffffffffu, prod, off);
        if (lane == ch) myscore = prod;
    }
    float ex = expf(myscore);   // global-max shift omitted: alpha-invariant (eps ~1e-16)
    g_exps[(size_t)e * 32 + lane] = ex;
    atomicAdd(&g_denom[(size_t)dst * 32 + lane], ex);
}

// ---------------- scatter: proj accumulation via vectorized red ----------
__device__ __forceinline__ void red_add_v4(float* p, float4 v) {
    asm volatile("red.global.add.v4.f32 [%0], {%1,%2,%3,%4};"
                 :: "l"(p), "f"(v.x), "f"(v.y), "f"(v.z), "f"(v.w) : "memory");
}

__global__ __launch_bounds__(256) void scatter_kernel(
    const int* __restrict__ edge_index, const int* __restrict__ bridge_index,
    float* __restrict__ out)
{
    __shared__ __align__(16) float pe_s[1024];
    for (int i = threadIdx.x; i < 1024; i += 256) pe_s[i] = g_pe[i];
    __syncthreads();
    const int e    = (blockIdx.x * 256 + threadIdx.x) >> 5;
    const int lane = threadIdx.x & 31;

    int fs, dst;
    if (e < E_EDGES)                 { fs = edge_index[e];              dst = edge_index[E_EDGES + e]; }
    else if (e < E_EDGES + B_BRIDGE) { int i = e - E_EDGES;             fs = bridge_index[i];            dst = bridge_index[B_BRIDGE + i]; }
    else                             { int i = e - E_EDGES - B_BRIDGE;  fs = bridge_index[B_BRIDGE + i]; dst = bridge_index[i]; }

    // faithful reference bug: x_src[full_src[e]] == xr[edge_index[0][full_src[e]]]
    const int s2 = edge_index[fs];

    float a = g_exps[(size_t)e * 32 + lane] /
              (g_denom[(size_t)dst * 32 + lane] + 1e-16f);

    const float4* xs = (const float4*)(g_xl + (size_t)s2 * DM);
    const int q = lane & 7;
    const int g = lane >> 3;
    float4 xv[8];
    #pragma unroll
    for (int h = 0; h < 8; h++) xv[h] = xs[h * 8 + q];

    float* ob = out + (size_t)dst * 1024;
    #pragma unroll
    for (int it = 0; it < 8; it++) {
        const int ch = g * 8 + it;
        float ach = __shfl_sync(0xffffffffu, a, ch);
        float4 p = *(const float4*)(pe_s + g * 256 + it * 32 + q * 4);
        float4 vv;
        vv.x = (xv[it].x + p.x) * ach;
        vv.y = (xv[it].y + p.y) * ach;
        vv.z = (xv[it].z + p.z) * ach;
        vv.w = (xv[it].w + p.w) * ach;
        red_add_v4(ob + ch * 32 + q * 4, vv);
    }
}

// ---------------- final PReLU -------------------------------------------
__global__ void prelu_kernel(float* __restrict__ out, const float* __restrict__ pw) {
    const float w = pw[0];
    size_t i = ((size_t)blockIdx.x * 256 + threadIdx.x) * 4;
    float4 v = *(float4*)(out + i);
    v.x = (v.x >= 0.f) ? v.x : w * v.x;
    v.y = (v.y >= 0.f) ? v.y : w * v.y;
    v.z = (v.z >= 0.f) ? v.z : w * v.z;
    v.w = (v.w >= 0.f) ? v.w : w * v.w;
    *(float4*)(out + i) = v;
}

// ---------------- launch --------------------------------------------------
extern "C" void kernel_launch(void* const* d_in, const int* in_sizes, int n_in,
                              void* d_out, int out_size) {
    const float* x            = (const float*)d_in[0];
    const int*   edge_index   = (const int*)  d_in[1];
    const int*   bridge_index = (const int*)  d_in[2];
    const float* W_in         = (const float*)d_in[3];
    const float* double_attn  = (const float*)d_in[4];
    const float* W_res        = (const float*)d_in[5];
    const float* bias         = (const float*)d_in[6];
    const float* prelu_w      = (const float*)d_in[7];
    float* out = (float*)d_out;

    cudaFuncSetAttribute(gemm_mma_kernel,
                         cudaFuncAttributeMaxDynamicSharedMemorySize, GEMM_SMEM);

    cudaStream_t s1;
    cudaStreamCreate(&s1);
    cudaEvent_t ev_fork, ev_xl, ev_sc;
    cudaEventCreateWithFlags(&ev_fork, cudaEventDisableTiming);
    cudaEventCreateWithFlags(&ev_xl,   cudaEventDisableTiming);
    cudaEventCreateWithFlags(&ev_sc,   cudaEventDisableTiming);

    // fork: init (pe + denom zeroing) runs on s1, independent of GEMM path
    cudaEventRecord(ev_fork, 0);
    cudaStreamWaitEvent(s1, ev_fork, 0);
    init_kernel<<<4096, 256, 0, s1>>>();

    // main stream: split + xl-GEMM, then residual GEMM
    prep_kernel<<<(NX4 + NW4 + 255) / 256, 256>>>(x, W_in, W_res);
    gemm_mma_kernel<<<dim3(2, 256), 256, GEMM_SMEM>>>(bias, out, 0);
    cudaEventRecord(ev_xl, 0);
    gemm_mma_kernel<<<dim3(8, 256), 256, GEMM_SMEM>>>(bias, out, 2);

    // side stream: scores needs g_xl (ev_xl) + init (ordered on s1)
    cudaStreamWaitEvent(s1, ev_xl, 0);
    scores_kernel<<<ET / 8, 256, 0, s1>>>(edge_index, bridge_index, double_attn);
    cudaEventRecord(ev_sc, s1);

    // join: scatter needs residual-out (stream 0) + scores (ev_sc)
    cudaStreamWaitEvent(0, ev_sc, 0);
    scatter_kernel<<<ET / 8, 256>>>(edge_index, bridge_index, out);
    prelu_kernel<<<(N_NODES * 1024) / (256 * 4), 256>>>(out, prelu_w);
}

// round 6
// speedup vs baseline: 1.7409x; 1.1054x over previous
#include <cuda_runtime.h>
#include <cuda_bf16.h>
#include <cstdint>

#define N_NODES 32768
#define F_DIM   128
#define C_CH    4
#define H_HEADS 8
#define D_DIM   32
#define DM      256
#define CHN     32          // C*H
#define E_EDGES 65536
#define B_BRIDGE 8192
#define ET      (E_EDGES + 2*B_BRIDGE)   // 81920
#define NW      1280        // total W rows (W_in 256 + W_res 1024)

// ---------------- device scratch (static, no allocation) ----------------
__device__ float g_xl[(size_t)N_NODES * DM];            // 33.5 MB
__device__ float g_exps[(size_t)ET * CHN];              // 10.5 MB
__device__ float g_pe[C_CH * DM];                       //  4 KB
__device__ __nv_bfloat16 g_xhi[(size_t)N_NODES * 128];  // 8.4 MB
__device__ __nv_bfloat16 g_xlo[(size_t)N_NODES * 128];  // 8.4 MB
__device__ __nv_bfloat16 g_whi[NW * 128];               // 328 KB
__device__ __nv_bfloat16 g_wlo[NW * 128];               // 328 KB
__device__ int g_cnt[N_NODES];                          // histogram
__device__ int g_rowptr[N_NODES + 1];                   // CSR offsets
__device__ int g_wcur[N_NODES];                         // fill cursors
__device__ int g_eids[ET];                              // CSR edge ids

__device__ __forceinline__ uint32_t smem_u32(const void* p) {
    uint32_t a;
    asm("{ .reg .u64 t; cvta.to.shared.u64 t, %1; cvt.u32.u64 %0, t; }"
        : "=r"(a) : "l"(p));
    return a;
}
__device__ __forceinline__ void cp16(uint32_t dst, const void* src) {
    asm volatile("cp.async.ca.shared.global [%0], [%1], 16;"
                 :: "r"(dst), "l"(src) : "memory");
}

// dst node of edge e (shared by hist/fill/scores)
__device__ __forceinline__ int edge_dst(int e, const int* __restrict__ ei,
                                        const int* __restrict__ bi) {
    if (e < E_EDGES)                 return ei[E_EDGES + e];
    if (e < E_EDGES + B_BRIDGE)      return bi[B_BRIDGE + (e - E_EDGES)];
    return bi[e - E_EDGES - B_BRIDGE];
}

// ---------------- init: zero histogram, compute sinusoidal PE ------------
__global__ void init_kernel() {
    int gid = blockIdx.x * 256 + threadIdx.x;
    if (gid < N_NODES) g_cnt[gid] = 0;
    if (gid < C_CH * DM) {
        int c  = gid >> 8;
        int hd = gid & 255;
        float di  = (float)(hd & ~1);
        float div = powf(10000.f, di / 256.f);
        float ang = (float)c / div;
        g_pe[gid] = (hd & 1) ? cosf(ang) : sinf(ang);
    }
}

// ---------------- CSR build ----------------------------------------------
__global__ void hist_kernel(const int* __restrict__ ei, const int* __restrict__ bi) {
    int e = blockIdx.x * 256 + threadIdx.x;
    if (e < ET) atomicAdd(&g_cnt[edge_dst(e, ei, bi)], 1);
}
__global__ void scan_kernel() {
    __shared__ int sd[1024];
    const int tid = threadIdx.x;
    int loc[32], sum = 0;
    const int base = tid * 32;
    #pragma unroll
    for (int k = 0; k < 32; k++) { loc[k] = g_cnt[base + k]; sum += loc[k]; }
    sd[tid] = sum; __syncthreads();
    for (int off = 1; off < 1024; off <<= 1) {
        int v = (tid >= off) ? sd[tid - off] : 0;
        __syncthreads();
        sd[tid] += v;
        __syncthreads();
    }
    int run = sd[tid] - sum;      // exclusive prefix
    #pragma unroll
    for (int k = 0; k < 32; k++) {
        g_rowptr[base + k] = run;
        g_wcur[base + k]   = run;
        run += loc[k];
    }
    if (tid == 1023) g_rowptr[N_NODES] = run;
}
__global__ void fill_kernel(const int* __restrict__ ei, const int* __restrict__ bi) {
    int e = blockIdx.x * 256 + threadIdx.x;
    if (e < ET) {
        int pos = atomicAdd(&g_wcur[edge_dst(e, ei, bi)], 1);
        g_eids[pos] = e;
    }
}

// ---------------- prep: split X and W into bf16 hi/lo ---------------------
#define NX4 ((N_NODES * 128) / 4)
#define NW4 ((NW * 128) / 4)
__global__ void prep_kernel(const float* __restrict__ x,
                            const float* __restrict__ W_in,
                            const float* __restrict__ W_res) {
    int gid = blockIdx.x * 256 + threadIdx.x;
    float4 v;
    __nv_bfloat16 *hi, *lo;
    if (gid < NX4) {
        v  = ((const float4*)x)[gid];
        hi = g_xhi; lo = g_xlo;
    } else if (gid < NX4 + NW4) {
        int j   = gid - NX4;
        int row = j >> 5;
        int c   = j & 31;
        const float* src = (row < 256) ? (W_in + (size_t)row * 128)
                                       : (W_res + (size_t)(row - 256) * 128);
        v  = ((const float4*)src)[c];
        hi = g_whi; lo = g_wlo;
        gid = j;
    } else return;
    __nv_bfloat162 h0 = __floats2bfloat162_rn(v.x, v.y);
    __nv_bfloat162 h1 = __floats2bfloat162_rn(v.z, v.w);
    __nv_bfloat162 l0 = __floats2bfloat162_rn(v.x - __bfloat162float(h0.x),
                                              v.y - __bfloat162float(h0.y));
    __nv_bfloat162 l1 = __floats2bfloat162_rn(v.z - __bfloat162float(h1.x),
                                              v.w - __bfloat162float(h1.y));
    ((uint2*)hi)[gid] = make_uint2(*(uint32_t*)&h0, *(uint32_t*)&h1);
    ((uint2*)lo)[gid] = make_uint2(*(uint32_t*)&l0, *(uint32_t*)&l1);
}

// ============== bf16-split mma.sync GEMM, 2-stage cp.async pipeline =======
// Block: 128m x 128n. K = 4 chunks of 32, double-buffered.
#define AST2 40                       // bf16 row stride: conflict-free
#define TS   (128 * AST2)             // tile elems (5120)
#define SS   (4 * TS)                 // stage elems (20480)
#define GEMM_SMEM (2 * SS * 2)        // bytes = 81920

__device__ __forceinline__ void mma_bf16(float* c, const uint32_t* a,
                                         uint32_t b0, uint32_t b1) {
    asm volatile(
        "mma.sync.aligned.m16n8k16.row.col.f32.bf16.bf16.f32 "
        "{%0,%1,%2,%3}, {%4,%5,%6,%7}, {%8,%9}, {%0,%1,%2,%3};"
        : "+f"(c[0]), "+f"(c[1]), "+f"(c[2]), "+f"(c[3])
        : "r"(a[0]), "r"(a[1]), "r"(a[2]), "r"(a[3]), "r"(b0), "r"(b1));
}

__global__ void __launch_bounds__(256, 2) gemm_mma_kernel(
    const float* __restrict__ bias, float* __restrict__ out, int nbase)
{
    extern __shared__ __align__(16) __nv_bfloat16 smem[];
    const int tid  = threadIdx.x;
    const int wid  = tid >> 5, lane = tid & 31;
    const int wr   = wid & 1;
    const int wc   = wid >> 1;
    const int m0   = blockIdx.y * 128;
    const int nb   = nbase + blockIdx.x;
    const int n0g  = nb * 128;
    const uint32_t sbase = smem_u32(smem);

    float acc[4][4][4];
    #pragma unroll
    for (int a = 0; a < 4; a++)
        #pragma unroll
        for (int b = 0; b < 4; b++)
            #pragma unroll
            for (int cc = 0; cc < 4; cc++) acc[a][b][cc] = 0.f;

    // stage chunk c (K cols kk..kk+31) into stage buffer s
    auto stage = [&](int c, int s) {
        const int kk = c * 32;
        const uint32_t sb = sbase + s * (SS * 2);
        #pragma unroll
        for (int r = 0; r < 8; r++) {
            int i = tid + r * 256;            // 2048 cp16 total
            int tile = i >> 9, j = i & 511;
            int row = j >> 2, c4 = j & 3;
            uint32_t doff = sb + tile * (TS * 2) + row * (AST2 * 2) + c4 * 16;
            const __nv_bfloat16* src;
            size_t go = (size_t)kk + c4 * 8;
            if      (tile == 0) src = g_xhi + (size_t)(m0 + row) * 128 + go;
            else if (tile == 1) src = g_xlo + (size_t)(m0 + row) * 128 + go;
            else if (tile == 2) src = g_whi + (size_t)(n0g + row) * 128 + go;
            else                src = g_wlo + (size_t)(n0g + row) * 128 + go;
            cp16(doff, src);
        }
        asm volatile("cp.async.commit_group;");
    };

    stage(0, 0);
    for (int c = 0; c < 4; c++) {
        if (c > 0) __syncthreads();           // buffer c&1 safe to overwrite
        if (c < 3) {
            stage(c + 1, (c + 1) & 1);
            asm volatile("cp.async.wait_group 1;" ::: "memory");
        } else {
            asm volatile("cp.async.wait_group 0;" ::: "memory");
        }
        __syncthreads();

        const __nv_bfloat16* Ahi = smem + (c & 1) * SS;
        const __nv_bfloat16* Alo = Ahi + TS;
        const __nv_bfloat16* Bhi = Ahi + 2 * TS;
        const __nv_bfloat16* Blo = Ahi + 3 * TS;
        const int mrow = wr * 64 + (lane >> 2);
        #pragma unroll
        for (int ks = 0; ks < 2; ks++) {
            const int kb = ks * 16 + 2 * (lane & 3);
            uint32_t ah[4][4], al[4][4];
            #pragma unroll
            for (int mi = 0; mi < 4; mi++) {
                int m = mrow + mi * 16;
                ah[mi][0] = *(const uint32_t*)(Ahi + m * AST2 + kb);
                ah[mi][1] = *(const uint32_t*)(Ahi + (m + 8) * AST2 + kb);
                ah[mi][2] = *(const uint32_t*)(Ahi + m * AST2 + kb + 8);
                ah[mi][3] = *(const uint32_t*)(Ahi + (m + 8) * AST2 + kb + 8);
                al[mi][0] = *(const uint32_t*)(Alo + m * AST2 + kb);
                al[mi][1] = *(const uint32_t*)(Alo + (m + 8) * AST2 + kb);
                al[mi][2] = *(const uint32_t*)(Alo + m * AST2 + kb + 8);
                al[mi][3] = *(const uint32_t*)(Alo + (m + 8) * AST2 + kb + 8);
            }
            #pragma unroll
            for (int ni = 0; ni < 4; ni++) {
                int n = wc * 32 + ni * 8 + (lane >> 2);
                uint32_t bh0 = *(const uint32_t*)(Bhi + n * AST2 + kb);
                uint32_t bh1 = *(const uint32_t*)(Bhi + n * AST2 + kb + 8);
                uint32_t bl0 = *(const uint32_t*)(Blo + n * AST2 + kb);
                uint32_t bl1 = *(const uint32_t*)(Blo + n * AST2 + kb + 8);
                #pragma unroll
                for (int mi = 0; mi < 4; mi++) {
                    mma_bf16(acc[mi][ni], ah[mi], bh0, bh1);
                    mma_bf16(acc[mi][ni], ah[mi], bl0, bl1);
                    mma_bf16(acc[mi][ni], al[mi], bh0, bh1);
                }
            }
        }
    }

    const int mrow = m0 + wr * 64 + (lane >> 2);
    const int ncol = wc * 32 + 2 * (lane & 3);
    #pragma unroll
    for (int mi = 0; mi < 4; mi++) {
        #pragma unroll
        for (int ni = 0; ni < 4; ni++) {
            int m = mrow + mi * 16;
            int nl = ncol + ni * 8;
            float* c = acc[mi][ni];
            if (nb < 2) {
                int col = n0g + nl;
                *(float2*)(g_xl + (size_t)m * 256 + col)       = make_float2(c[0], c[1]);
                *(float2*)(g_xl + (size_t)(m + 8) * 256 + col) = make_float2(c[2], c[3]);
            } else {
                int col = n0g - 256 + nl;
                float b0 = __ldg(bias + col), b1 = __ldg(bias + col + 1);
                *(float2*)(out + (size_t)m * 1024 + col)       = make_float2(c[0] + b0, c[1] + b1);
                *(float2*)(out + (size_t)(m + 8) * 1024 + col) = make_float2(c[2] + b0, c[3] + b1);
            }
        }
    }
}

// ---------------- scores: one warp per edge (exp only, no denom) ---------
__global__ __launch_bounds__(256) void scores_kernel(
    const int* __restrict__ edge_index, const int* __restrict__ bridge_index,
    const float* __restrict__ double_attn)
{
    __shared__ float pe_s[1024];
    __shared__ float aw_s[1024];
    for (int i = threadIdx.x; i < 1024; i += 256) {
        pe_s[i] = g_pe[i];
        aw_s[i] = double_attn[i];
    }
    __syncthreads();
    const int e    = (blockIdx.x * 256 + threadIdx.x) >> 5;
    const int lane = threadIdx.x & 31;

    int u, v, type;
    if (e < E_EDGES)                { u = edge_index[e];   v = edge_index[E_EDGES + e];   type = 0; }
    else if (e < E_EDGES + B_BRIDGE){ int i = e - E_EDGES;            u = bridge_index[i]; v = bridge_index[B_BRIDGE + i]; type = 1; }
    else                            { int i = e - E_EDGES - B_BRIDGE; u = bridge_index[i]; v = bridge_index[B_BRIDGE + i]; type = 2; }

    const float* xu = g_xl + (size_t)u * DM;
    const float* xv = g_xl + (size_t)v * DM;
    float S[8];
    #pragma unroll
    for (int h = 0; h < 8; h++) S[h] = xu[h * 32 + lane] + xv[h * 32 + lane];

    float myscore = 0.f;
    #pragma unroll
    for (int ch = 0; ch < 32; ch++) {
        const int c = ch >> 3, h = ch & 7;
        int c2;
        if (type == 0)      c2 = c;
        else if (type == 1) c2 = (c < 3) ? c + 1 : 3;
        else                c2 = (c > 0) ? c - 1 : 0;
        float t = S[h] + pe_s[c * 256 + h * 32 + lane] + pe_s[c2 * 256 + h * 32 + lane];
        t = (t >= 0.f) ? t : 0.2f * t;
        bool masked = (type == 1 && c == 3) || (type == 2 && c == 0);
        float prod = masked ? 0.f : t * aw_s[ch * 32 + lane];
        #pragma unroll
        for (int off = 16; off; off >>= 1)
            prod += __shfl_xor_sync(0xffffffffu, prod, off);
        if (lane == ch) myscore = prod;
    }
    g_exps[(size_t)e * 32 + lane] = expf(myscore);   // max-shift alpha-invariant
}

// ---------------- node-major scatter + residual + PReLU (fused) ----------
__global__ __launch_bounds__(256) void scatter_fused_kernel(
    const int* __restrict__ edge_index, const int* __restrict__ bridge_index,
    float* __restrict__ out, const float* __restrict__ pw)
{
    __shared__ __align__(16) float pe_s[1024];
    for (int i = threadIdx.x; i < 1024; i += 256) pe_s[i] = g_pe[i];
    __syncthreads();
    const int n    = blockIdx.x * 8 + (threadIdx.x >> 5);   // node id
    const int lane = threadIdx.x & 31;
    const int start = g_rowptr[n], end = g_rowptr[n + 1];

    // pass 1: denominator (lane = channel)
    float dsum = 0.f;
    for (int j = start; j < end; j++)
        dsum += g_exps[(size_t)g_eids[j] * 32 + lane];
    const float inv = 1.f / (dsum + 1e-16f);

    // pass 2: weighted accumulation, lane owns (g = c, q = d-quad)
    const int q = lane & 7;
    const int g = lane >> 3;
    float4 accv[8];
    #pragma unroll
    for (int it = 0; it < 8; it++) accv[it] = make_float4(0.f, 0.f, 0.f, 0.f);

    for (int j = start; j < end; j++) {
        const int e = g_eids[j];
        int fs;
        if (e < E_EDGES)                 fs = edge_index[e];
        else if (e < E_EDGES + B_BRIDGE) fs = bridge_index[e - E_EDGES];
        else                             fs = bridge_index[B_BRIDGE + (e - E_EDGES - B_BRIDGE)];
        const int s2 = edge_index[fs];   // faithful reference bug

        const float a = g_exps[(size_t)e * 32 + lane] * inv;   // lane = ch

        const float4* xs = (const float4*)(g_xl + (size_t)s2 * DM);
        float4 xv[8];
        #pragma unroll
        for (int h = 0; h < 8; h++) xv[h] = xs[h * 8 + q];

        #pragma unroll
        for (int it = 0; it < 8; it++) {
            const int ch = g * 8 + it;
            const float ach = __shfl_sync(0xffffffffu, a, ch);
            const float4 p = *(const float4*)(pe_s + g * 256 + it * 32 + q * 4);
            accv[it].x += (xv[it].x + p.x) * ach;
            accv[it].y += (xv[it].y + p.y) * ach;
            accv[it].z += (xv[it].z + p.z) * ach;
            accv[it].w += (xv[it].w + p.w) * ach;
        }
    }

    // epilogue: + residual(+bias, already in out), PReLU, single store
    const float w = pw[0];
    float* ob = out + (size_t)n * 1024;
    #pragma unroll
    for (int it = 0; it < 8; it++) {
        const int idx = (g * 8 + it) * 32 + q * 4;
        float4 r = *(const float4*)(ob + idx);
        r.x += accv[it].x; r.y += accv[it].y; r.z += accv[it].z; r.w += accv[it].w;
        r.x = (r.x >= 0.f) ? r.x : w * r.x;
        r.y = (r.y >= 0.f) ? r.y : w * r.y;
        r.z = (r.z >= 0.f) ? r.z : w * r.z;
        r.w = (r.w >= 0.f) ? r.w : w * r.w;
        *(float4*)(ob + idx) = r;
    }
}

// ---------------- launch --------------------------------------------------
extern "C" void kernel_launch(void* const* d_in, const int* in_sizes, int n_in,
                              void* d_out, int out_size) {
    const float* x            = (const float*)d_in[0];
    const int*   edge_index   = (const int*)  d_in[1];
    const int*   bridge_index = (const int*)  d_in[2];
    const float* W_in         = (const float*)d_in[3];
    const float* double_attn  = (const float*)d_in[4];
    const float* W_res        = (const float*)d_in[5];
    const float* bias         = (const float*)d_in[6];
    const float* prelu_w      = (const float*)d_in[7];
    float* out = (float*)d_out;

    cudaFuncSetAttribute(gemm_mma_kernel,
                         cudaFuncAttributeMaxDynamicSharedMemorySize, GEMM_SMEM);

    cudaStream_t s1;
    cudaStreamCreate(&s1);
    cudaEvent_t ev_fork, ev_xl, ev_sc;
    cudaEventCreateWithFlags(&ev_fork, cudaEventDisableTiming);
    cudaEventCreateWithFlags(&ev_xl,   cudaEventDisableTiming);
    cudaEventCreateWithFlags(&ev_sc,   cudaEventDisableTiming);

    // side stream: PE + CSR build (independent of GEMM path)
    cudaEventRecord(ev_fork, 0);
    cudaStreamWaitEvent(s1, ev_fork, 0);
    init_kernel<<<(N_NODES + 255) / 256, 256, 0, s1>>>();
    hist_kernel<<<ET / 256, 256, 0, s1>>>(edge_index, bridge_index);
    scan_kernel<<<1, 1024, 0, s1>>>();
    fill_kernel<<<ET / 256, 256, 0, s1>>>(edge_index, bridge_index);

    // main stream: split + xl-GEMM, then residual GEMM
    prep_kernel<<<(NX4 + NW4 + 255) / 256, 256>>>(x, W_in, W_res);
    gemm_mma_kernel<<<dim3(2, 256), 256, GEMM_SMEM>>>(bias, out, 0);
    cudaEventRecord(ev_xl, 0);
    gemm_mma_kernel<<<dim3(8, 256), 256, GEMM_SMEM>>>(bias, out, 2);

    // side stream: scores needs g_xl + PE (ordered on s1)
    cudaStreamWaitEvent(s1, ev_xl, 0);
    scores_kernel<<<ET / 8, 256, 0, s1>>>(edge_index, bridge_index, double_attn);
    cudaEventRecord(ev_sc, s1);

    // join: fused scatter needs residual-out (stream 0) + scores + CSR (ev_sc)
    cudaStreamWaitEvent(0, ev_sc, 0);
    scatter_fused_kernel<<<N_NODES / 8, 256>>>(edge_index, bridge_index, out, prelu_w);
}

// round 7
// speedup vs baseline: 2.0008x; 1.1493x over previous
#include <cuda_runtime.h>
#include <cuda_bf16.h>
#include <cstdint>

#define N_NODES 32768
#define F_DIM   128
#define C_CH    4
#define H_HEADS 8
#define D_DIM   32
#define DM      256
#define CHN     32          // C*H
#define E_EDGES 65536
#define B_BRIDGE 8192
#define ET      (E_EDGES + 2*B_BRIDGE)   // 81920
#define NW      1280        // total W rows (W_in 256 + W_res 1024)

// ---------------- device scratch (static, no allocation) ----------------
__device__ float g_xl[(size_t)N_NODES * DM];            // 33.5 MB
__device__ float g_exps[(size_t)ET * CHN];              // 10.5 MB
__device__ float g_pe[C_CH * DM];                       //  4 KB
__device__ __nv_bfloat16 g_xhi[(size_t)N_NODES * 128];  // 8.4 MB
__device__ __nv_bfloat16 g_xlo[(size_t)N_NODES * 128];  // 8.4 MB
__device__ __nv_bfloat16 g_whi[NW * 128];               // 328 KB
__device__ __nv_bfloat16 g_wlo[NW * 128];               // 328 KB
__device__ int g_cnt[N_NODES];
__device__ int g_rowptr[N_NODES + 1];
__device__ int g_wcur[N_NODES];
__device__ int g_eids[ET];

__device__ __forceinline__ uint32_t smem_u32(const void* p) {
    uint32_t a;
    asm("{ .reg .u64 t; cvta.to.shared.u64 t, %1; cvt.u32.u64 %0, t; }"
        : "=r"(a) : "l"(p));
    return a;
}
__device__ __forceinline__ void cp16(uint32_t dst, const void* src) {
    asm volatile("cp.async.ca.shared.global [%0], [%1], 16;"
                 :: "r"(dst), "l"(src) : "memory");
}
__device__ __forceinline__ void ldm_x4(uint32_t* r, uint32_t addr) {
    asm volatile("ldmatrix.sync.aligned.m8n8.x4.shared.b16 {%0,%1,%2,%3}, [%4];"
                 : "=r"(r[0]), "=r"(r[1]), "=r"(r[2]), "=r"(r[3]) : "r"(addr));
}

__device__ __forceinline__ int edge_dst(int e, const int* __restrict__ ei,
                                        const int* __restrict__ bi) {
    if (e < E_EDGES)                 return ei[E_EDGES + e];
    if (e < E_EDGES + B_BRIDGE)      return bi[B_BRIDGE + (e - E_EDGES)];
    return bi[e - E_EDGES - B_BRIDGE];
}

// ---------------- init: zero histogram, compute sinusoidal PE ------------
__global__ void init_kernel() {
    int gid = blockIdx.x * 256 + threadIdx.x;
    if (gid < N_NODES) g_cnt[gid] = 0;
    if (gid < C_CH * DM) {
        int c  = gid >> 8;
        int hd = gid & 255;
        float di  = (float)(hd & ~1);
        float div = powf(10000.f, di / 256.f);
        float ang = (float)c / div;
        g_pe[gid] = (hd & 1) ? cosf(ang) : sinf(ang);
    }
}

// ---------------- CSR build ----------------------------------------------
__global__ void hist_kernel(const int* __restrict__ ei, const int* __restrict__ bi) {
    int e = blockIdx.x * 256 + threadIdx.x;
    if (e < ET) atomicAdd(&g_cnt[edge_dst(e, ei, bi)], 1);
}
__global__ void scan_kernel() {
    __shared__ int sd[1024];
    const int tid = threadIdx.x;
    int loc[32], sum = 0;
    const int base = tid * 32;
    #pragma unroll
    for (int k = 0; k < 32; k++) { loc[k] = g_cnt[base + k]; sum += loc[k]; }
    sd[tid] = sum; __syncthreads();
    for (int off = 1; off < 1024; off <<= 1) {
        int v = (tid >= off) ? sd[tid - off] : 0;
        __syncthreads();
        sd[tid] += v;
        __syncthreads();
    }
    int run = sd[tid] - sum;
    #pragma unroll
    for (int k = 0; k < 32; k++) {
        g_rowptr[base + k] = run;
        g_wcur[base + k]   = run;
        run += loc[k];
    }
    if (tid == 1023) g_rowptr[N_NODES] = run;
}
__global__ void fill_kernel(const int* __restrict__ ei, const int* __restrict__ bi) {
    int e = blockIdx.x * 256 + threadIdx.x;
    if (e < ET) {
        int pos = atomicAdd(&g_wcur[edge_dst(e, ei, bi)], 1);
        g_eids[pos] = e;
    }
}

// ---------------- prep: split X and W into bf16 hi/lo ---------------------
#define NX4 ((N_NODES * 128) / 4)
#define NW4 ((NW * 128) / 4)
__global__ void prep_kernel(const float* __restrict__ x,
                            const float* __restrict__ W_in,
                            const float* __restrict__ W_res) {
    int gid = blockIdx.x * 256 + threadIdx.x;
    float4 v;
    __nv_bfloat16 *hi, *lo;
    if (gid < NX4) {
        v  = ((const float4*)x)[gid];
        hi = g_xhi; lo = g_xlo;
    } else if (gid < NX4 + NW4) {
        int j   = gid - NX4;
        int row = j >> 5;
        int c   = j & 31;
        const float* src = (row < 256) ? (W_in + (size_t)row * 128)
                                       : (W_res + (size_t)(row - 256) * 128);
        v  = ((const float4*)src)[c];
        hi = g_whi; lo = g_wlo;
        gid = j;
    } else return;
    __nv_bfloat162 h0 = __floats2bfloat162_rn(v.x, v.y);
    __nv_bfloat162 h1 = __floats2bfloat162_rn(v.z, v.w);
    __nv_bfloat162 l0 = __floats2bfloat162_rn(v.x - __bfloat162float(h0.x),
                                              v.y - __bfloat162float(h0.y));
    __nv_bfloat162 l1 = __floats2bfloat162_rn(v.z - __bfloat162float(h1.x),
                                              v.w - __bfloat162float(h1.y));
    ((uint2*)hi)[gid] = make_uint2(*(uint32_t*)&h0, *(uint32_t*)&h1);
    ((uint2*)lo)[gid] = make_uint2(*(uint32_t*)&l0, *(uint32_t*)&l1);
}

// ============== bf16-split mma.sync GEMM, cp.async + ldmatrix =============
#define AST2 40                       // bf16 row stride (80 B): LDSM conflict-free
#define TS   (128 * AST2)             // tile elems (5120)
#define SS   (4 * TS)                 // stage elems (20480)
#define GEMM_SMEM (2 * SS * 2)        // 81920 B

__device__ __forceinline__ void mma_bf16(float* c, const uint32_t* a,
                                         uint32_t b0, uint32_t b1) {
    asm volatile(
        "mma.sync.aligned.m16n8k16.row.col.f32.bf16.bf16.f32 "
        "{%0,%1,%2,%3}, {%4,%5,%6,%7}, {%8,%9}, {%0,%1,%2,%3};"
        : "+f"(c[0]), "+f"(c[1]), "+f"(c[2]), "+f"(c[3])
        : "r"(a[0]), "r"(a[1]), "r"(a[2]), "r"(a[3]), "r"(b0), "r"(b1));
}

__global__ void __launch_bounds__(256, 2) gemm_mma_kernel(
    const float* __restrict__ bias, float* __restrict__ out, int nbase)
{
    extern __shared__ __align__(16) __nv_bfloat16 smem[];
    const int tid  = threadIdx.x;
    const int wid  = tid >> 5, lane = tid & 31;
    const int wr   = wid & 1;
    const int wc   = wid >> 1;
    const int m0   = blockIdx.y * 128;
    const int nb   = nbase + blockIdx.x;
    const int n0g  = nb * 128;
    const uint32_t sbase = smem_u32(smem);

    // ldmatrix lane address components (elements)
    const int aIdx = (wr * 64 + (lane & 7) + ((lane >> 3) & 1) * 8) * AST2
                   + ((lane >> 4) & 1) * 8;
    const int bIdx = (wc * 32 + ((lane >> 4) & 1) * 8 + (lane & 7)) * AST2
                   + ((lane >> 3) & 1) * 8;

    float acc[4][4][4];
    #pragma unroll
    for (int a = 0; a < 4; a++)
        #pragma unroll
        for (int b = 0; b < 4; b++)
            #pragma unroll
            for (int cc = 0; cc < 4; cc++) acc[a][b][cc] = 0.f;

    auto stage = [&](int c, int s) {
        const int kk = c * 32;
        const uint32_t sb = sbase + s * (SS * 2);
        #pragma unroll
        for (int r = 0; r < 8; r++) {
            int i = tid + r * 256;
            int tile = i >> 9, j = i & 511;
            int row = j >> 2, c4 = j & 3;
            uint32_t doff = sb + tile * (TS * 2) + row * (AST2 * 2) + c4 * 16;
            const __nv_bfloat16* src;
            size_t go = (size_t)kk + c4 * 8;
            if      (tile == 0) src = g_xhi + (size_t)(m0 + row) * 128 + go;
            else if (tile == 1) src = g_xlo + (size_t)(m0 + row) * 128 + go;
            else if (tile == 2) src = g_whi + (size_t)(n0g + row) * 128 + go;
            else                src = g_wlo + (size_t)(n0g + row) * 128 + go;
            cp16(doff, src);
        }
        asm volatile("cp.async.commit_group;");
    };

    stage(0, 0);
    for (int c = 0; c < 4; c++) {
        if (c > 0) __syncthreads();
        if (c < 3) {
            stage(c + 1, (c + 1) & 1);
            asm volatile("cp.async.wait_group 1;" ::: "memory");
        } else {
            asm volatile("cp.async.wait_group 0;" ::: "memory");
        }
        __syncthreads();

        const uint32_t bufb = sbase + (c & 1) * (SS * 2);
        #pragma unroll
        for (int ks = 0; ks < 2; ks++) {
            const int k0 = ks * 16;
            uint32_t ah[4][4], al[4][4], Bh[2][4], Bl[2][4];
            const uint32_t aAddr = bufb + (aIdx + k0) * 2;
            const uint32_t bAddr = bufb + 2 * (TS * 2) + (bIdx + k0) * 2;
            #pragma unroll
            for (int mi = 0; mi < 4; mi++) {
                ldm_x4(ah[mi], aAddr + mi * (16 * AST2 * 2));
                ldm_x4(al[mi], aAddr + (TS * 2) + mi * (16 * AST2 * 2));
            }
            #pragma unroll
            for (int np = 0; np < 2; np++) {
                ldm_x4(Bh[np], bAddr + np * (16 * AST2 * 2));
                ldm_x4(Bl[np], bAddr + (TS * 2) + np * (16 * AST2 * 2));
            }
            #pragma unroll
            for (int ni = 0; ni < 4; ni++) {
                const int np = ni >> 1, hf = (ni & 1) * 2;
                const uint32_t bh0 = Bh[np][hf], bh1 = Bh[np][hf + 1];
                const uint32_t bl0 = Bl[np][hf], bl1 = Bl[np][hf + 1];
                #pragma unroll
                for (int mi = 0; mi < 4; mi++) {
                    mma_bf16(acc[mi][ni], ah[mi], bh0, bh1);
                    mma_bf16(acc[mi][ni], ah[mi], bl0, bl1);
                    mma_bf16(acc[mi][ni], al[mi], bh0, bh1);
                }
            }
        }
    }

    const int mrow = m0 + wr * 64 + (lane >> 2);
    const int ncol = wc * 32 + 2 * (lane & 3);
    #pragma unroll
    for (int mi = 0; mi < 4; mi++) {
        #pragma unroll
        for (int ni = 0; ni < 4; ni++) {
            int m = mrow + mi * 16;
            int nl = ncol + ni * 8;
            float* c = acc[mi][ni];
            if (nb < 2) {
                int col = n0g + nl;
                *(float2*)(g_xl + (size_t)m * 256 + col)       = make_float2(c[0], c[1]);
                *(float2*)(g_xl + (size_t)(m + 8) * 256 + col) = make_float2(c[2], c[3]);
            } else {
                int col = n0g - 256 + nl;
                float b0 = __ldg(bias + col), b1 = __ldg(bias + col + 1);
                *(float2*)(out + (size_t)m * 1024 + col)       = make_float2(c[0] + b0, c[1] + b1);
                *(float2*)(out + (size_t)(m + 8) * 1024 + col) = make_float2(c[2] + b0, c[3] + b1);
            }
        }
    }
}

// ---------------- scores: one warp per edge, 31-shfl transpose reduce ----
__global__ __launch_bounds__(256) void scores_kernel(
    const int* __restrict__ edge_index, const int* __restrict__ bridge_index,
    const float* __restrict__ double_attn)
{
    __shared__ float pe_s[1024];
    __shared__ float aw_s[1024];
    for (int i = threadIdx.x; i < 1024; i += 256) {
        pe_s[i] = g_pe[i];
        aw_s[i] = double_attn[i];
    }
    __syncthreads();
    const int e    = (blockIdx.x * 256 + threadIdx.x) >> 5;
    const int lane = threadIdx.x & 31;

    int u, v, type;
    if (e < E_EDGES)                { u = edge_index[e];   v = edge_index[E_EDGES + e];   type = 0; }
    else if (e < E_EDGES + B_BRIDGE){ int i = e - E_EDGES;            u = bridge_index[i]; v = bridge_index[B_BRIDGE + i]; type = 1; }
    else                            { int i = e - E_EDGES - B_BRIDGE; u = bridge_index[i]; v = bridge_index[B_BRIDGE + i]; type = 2; }

    const float* xu = g_xl + (size_t)u * DM;
    const float* xv = g_xl + (size_t)v * DM;
    float S[8];
    #pragma unroll
    for (int h = 0; h < 8; h++) S[h] = xu[h * 32 + lane] + xv[h * 32 + lane];

    // per-lane (lane = d) products for all 32 channels
    float vch[32];
    #pragma unroll
    for (int ch = 0; ch < 32; ch++) {
        const int c = ch >> 3, h = ch & 7;
        int c2;
        if (type == 0)      c2 = c;
        else if (type == 1) c2 = (c < 3) ? c + 1 : 3;
        else                c2 = (c > 0) ? c - 1 : 0;
        float t = S[h] + pe_s[c * 256 + h * 32 + lane] + pe_s[c2 * 256 + h * 32 + lane];
        t = (t >= 0.f) ? t : 0.2f * t;
        bool masked = (type == 1 && c == 3) || (type == 2 && c == 0);
        vch[ch] = masked ? 0.f : t * aw_s[ch * 32 + lane];
    }
    // multi-value butterfly: 31 shfl; lane ends with sum over d of vch[lane]
    #pragma unroll
    for (int off = 16; off; off >>= 1) {
        const bool up = (lane & off) != 0;
        #pragma unroll
        for (int k = 0; k < off; k++) {
            float sent = up ? vch[k] : vch[k + off];
            float recv = __shfl_xor_sync(0xffffffffu, sent, off);
            vch[k] = (up ? vch[k + off] : vch[k]) + recv;
        }
    }
    g_exps[(size_t)e * 32 + lane] = expf(vch[0]);  // max-shift alpha-invariant
}

// ---------------- node-major scatter + residual + PReLU (fused) ----------
__global__ __launch_bounds__(256) void scatter_fused_kernel(
    const int* __restrict__ edge_index, const int* __restrict__ bridge_index,
    float* __restrict__ out, const float* __restrict__ pw)
{
    __shared__ __align__(16) float pe_s[1024];
    for (int i = threadIdx.x; i < 1024; i += 256) pe_s[i] = g_pe[i];
    __syncthreads();
    const int n    = blockIdx.x * 8 + (threadIdx.x >> 5);
    const int lane = threadIdx.x & 31;
    const int start = g_rowptr[n], end = g_rowptr[n + 1];

    float dsum = 0.f;
    for (int j = start; j < end; j++)
        dsum += g_exps[(size_t)g_eids[j] * 32 + lane];
    const float inv = 1.f / (dsum + 1e-16f);

    const int q = lane & 7;
    const int g = lane >> 3;
    float4 accv[8];
    #pragma unroll
    for (int it = 0; it < 8; it++) accv[it] = make_float4(0.f, 0.f, 0.f, 0.f);

    for (int j = start; j < end; j++) {
        const int e = g_eids[j];
        int fs;
        if (e < E_EDGES)                 fs = edge_index[e];
        else if (e < E_EDGES + B_BRIDGE) fs = bridge_index[e - E_EDGES];
        else                             fs = bridge_index[B_BRIDGE + (e - E_EDGES - B_BRIDGE)];
        const int s2 = edge_index[fs];   // faithful reference bug

        const float a = g_exps[(size_t)e * 32 + lane] * inv;

        const float4* xs = (const float4*)(g_xl + (size_t)s2 * DM);
        float4 xv[8];
        #pragma unroll
        for (int h = 0; h < 8; h++) xv[h] = xs[h * 8 + q];

        #pragma unroll
        for (int it = 0; it < 8; it++) {
            const int ch = g * 8 + it;
            const float ach = __shfl_sync(0xffffffffu, a, ch);
            const float4 p = *(const float4*)(pe_s + g * 256 + it * 32 + q * 4);
            accv[it].x += (xv[it].x + p.x) * ach;
            accv[it].y += (xv[it].y + p.y) * ach;
            accv[it].z += (xv[it].z + p.z) * ach;
            accv[it].w += (xv[it].w + p.w) * ach;
        }
    }

    const float w = pw[0];
    float* ob = out + (size_t)n * 1024;
    #pragma unroll
    for (int it = 0; it < 8; it++) {
        const int idx = (g * 8 + it) * 32 + q * 4;
        float4 r = *(const float4*)(ob + idx);
        r.x += accv[it].x; r.y += accv[it].y; r.z += accv[it].z; r.w += accv[it].w;
        r.x = (r.x >= 0.f) ? r.x : w * r.x;
        r.y = (r.y >= 0.f) ? r.y : w * r.y;
        r.z = (r.z >= 0.f) ? r.z : w * r.z;
        r.w = (r.w >= 0.f) ? r.w : w * r.w;
        *(float4*)(ob + idx) = r;
    }
}

// ---------------- launch --------------------------------------------------
extern "C" void kernel_launch(void* const* d_in, const int* in_sizes, int n_in,
                              void* d_out, int out_size) {
    const float* x            = (const float*)d_in[0];
    const int*   edge_index   = (const int*)  d_in[1];
    const int*   bridge_index = (const int*)  d_in[2];
    const float* W_in         = (const float*)d_in[3];
    const float* double_attn  = (const float*)d_in[4];
    const float* W_res        = (const float*)d_in[5];
    const float* bias         = (const float*)d_in[6];
    const float* prelu_w      = (const float*)d_in[7];
    float* out = (float*)d_out;

    cudaFuncSetAttribute(gemm_mma_kernel,
                         cudaFuncAttributeMaxDynamicSharedMemorySize, GEMM_SMEM);

    cudaStream_t s1;
    cudaStreamCreate(&s1);
    cudaEvent_t ev_fork, ev_xl, ev_sc;
    cudaEventCreateWithFlags(&ev_fork, cudaEventDisableTiming);
    cudaEventCreateWithFlags(&ev_xl,   cudaEventDisableTiming);
    cudaEventCreateWithFlags(&ev_sc,   cudaEventDisableTiming);

    cudaEventRecord(ev_fork, 0);
    cudaStreamWaitEvent(s1, ev_fork, 0);
    init_kernel<<<(N_NODES + 255) / 256, 256, 0, s1>>>();
    hist_kernel<<<ET / 256, 256, 0, s1>>>(edge_index, bridge_index);
    scan_kernel<<<1, 1024, 0, s1>>>();
    fill_kernel<<<ET / 256, 256, 0, s1>>>(edge_index, bridge_index);

    prep_kernel<<<(NX4 + NW4 + 255) / 256, 256>>>(x, W_in, W_res);
    gemm_mma_kernel<<<dim3(2, 256), 256, GEMM_SMEM>>>(bias, out, 0);
    cudaEventRecord(ev_xl, 0);
    gemm_mma_kernel<<<dim3(8, 256), 256, GEMM_SMEM>>>(bias, out, 2);

    cudaStreamWaitEvent(s1, ev_xl, 0);
    scores_kernel<<<ET / 8, 256, 0, s1>>>(edge_index, bridge_index, double_attn);
    cudaEventRecord(ev_sc, s1);

    cudaStreamWaitEvent(0, ev_sc, 0);
    scatter_fused_kernel<<<N_NODES / 8, 256>>>(edge_index, bridge_index, out, prelu_w);
}